// round 7
// baseline (speedup 1.0000x reference)
#include <cuda_runtime.h>

#define T_LEN 16384
#define NXW   128
#define NH    512
#define STEPS (T_LEN - NXW)       /* 16256 */
#define NROWS (4 * NH)            /* 2048 gate rows */

#define NCTA  128
#define TPB   128                 /* 4 warps -> 512 warps total = NH */
#define WPC   (TPB / 32)

/* padded smem index: +4 floats per 32-entry group -> conflict-free LDS.128 */
#define SIDX(e) ((e) + (((e) >> 5) << 2))

/* ---- static scratch ---- */
__device__ __align__(16) float  g_XG[(size_t)NROWS * STEPS];     /* [row][t], row=h*4+g */
__device__ __align__(16) float2 g_HP[(size_t)(STEPS + 1) * NH];  /* (h_value, tag_bits) */

/* =================== init =================== */
__global__ void init_kernel() {
    int i = blockIdx.x * blockDim.x + threadIdx.x;
    if (i < NH) g_HP[i] = make_float2(0.0f, __uint_as_float(0u));
}

/* =================== gate precompute =================== */
#define GT_TPB  128
#define GT_TT   512
#define GT_ROWS 16

__global__ void __launch_bounds__(GT_TPB) gates_kernel(
    const float* __restrict__ x,
    const float* __restrict__ Wf, const float* __restrict__ Wi,
    const float* __restrict__ Wo, const float* __restrict__ Wc,
    const float* __restrict__ bf, const float* __restrict__ bi,
    const float* __restrict__ bo, const float* __restrict__ bc)
{
    __shared__ float xs[GT_TT + NXW];
    __shared__ float ws[GT_ROWS * NXW];
    __shared__ float bs[GT_ROWS];

    const int tid = threadIdx.x;
    const int t0  = blockIdx.x * GT_TT;
    const int r0  = blockIdx.y * GT_ROWS;

    for (int i = tid; i < GT_TT + NXW; i += GT_TPB) {
        int xi = t0 + i;
        xs[i] = (xi < T_LEN) ? x[xi] : 0.0f;
    }
    for (int i = tid; i < GT_ROWS * NXW; i += GT_TPB) {
        int lr = i >> 7;
        int k  = i & 127;
        int r  = r0 + lr;
        int g  = r & 3;
        int h  = r >> 2;
        const float* W = (g == 0) ? Wf : (g == 1) ? Wi : (g == 2) ? Wo : Wc;
        ws[i] = W[h * NXW + k];
    }
    if (tid < GT_ROWS) {
        int r = r0 + tid;
        int g = r & 3;
        int h = r >> 2;
        const float* B = (g == 0) ? bf : (g == 1) ? bi : (g == 2) ? bo : bc;
        bs[tid] = B[h];
    }
    __syncthreads();

    float acc0[GT_ROWS], acc1[GT_ROWS], acc2[GT_ROWS], acc3[GT_ROWS];
#pragma unroll
    for (int lr = 0; lr < GT_ROWS; lr++) { acc0[lr] = acc1[lr] = acc2[lr] = acc3[lr] = 0.0f; }

#pragma unroll 4
    for (int k = 0; k < NXW; k++) {
        float x0 = xs[tid + k];
        float x1 = xs[tid + 128 + k];
        float x2 = xs[tid + 256 + k];
        float x3 = xs[tid + 384 + k];
#pragma unroll
        for (int lr = 0; lr < GT_ROWS; lr++) {
            float w = ws[lr * NXW + k];
            acc0[lr] = fmaf(w, x0, acc0[lr]);
            acc1[lr] = fmaf(w, x1, acc1[lr]);
            acc2[lr] = fmaf(w, x2, acc2[lr]);
            acc3[lr] = fmaf(w, x3, acc3[lr]);
        }
    }

#pragma unroll
    for (int lr = 0; lr < GT_ROWS; lr++) {
        size_t base = (size_t)(r0 + lr) * STEPS;
        int t;
        t = t0 + tid;       if (t < STEPS) g_XG[base + t] = acc0[lr] + bs[lr];
        t = t0 + 128 + tid; if (t < STEPS) g_XG[base + t] = acc1[lr] + bs[lr];
        t = t0 + 256 + tid; if (t < STEPS) g_XG[base + t] = acc2[lr] + bs[lr];
        t = t0 + 384 + tid; if (t < STEPS) g_XG[base + t] = acc3[lr] + bs[lr];
    }
}

/* =================== recurrence =================== */
__device__ __forceinline__ float sigmoid_f(float v) {
    float e = __expf(-v);
    return __fdividef(1.0f, 1.0f + e);
}
__device__ __forceinline__ float tanh_f(float v) {
    float e = __expf(2.0f * v);
    return __fdividef(e - 1.0f, e + 1.0f);
}

__device__ __forceinline__ float4 poll_ld(const void* p) {
    float4 v;
    asm volatile("ld.global.cg.v4.f32 {%0,%1,%2,%3}, [%4];"
                 : "=f"(v.x), "=f"(v.y), "=f"(v.z), "=f"(v.w)
                 : "l"(p) : "memory");
    return v;
}

__device__ __forceinline__ void ffma2(unsigned long long& d,
                                      unsigned long long a,
                                      unsigned long long b) {
    asm("fma.rn.f32x2 %0, %1, %2, %0;" : "+l"(d) : "l"(a), "l"(b));
}

__global__ void __launch_bounds__(TPB, 1) rec_kernel(
    const float* __restrict__ Uf, const float* __restrict__ Ui,
    const float* __restrict__ Uo, const float* __restrict__ Uc)
{
    const int tid   = threadIdx.x;
    const int w     = tid >> 5;
    const int lane  = tid & 31;
    const int h_idx = blockIdx.x * WPC + w;      /* one warp per hidden unit */

    /* shared h row (values only), padded for conflict-free float4 access */
    __shared__ __align__(16) float sh[SIDX(NH)];

    /* U weights as f32x2 pairs: lane L covers entries [16L, 16L+16) */
    const float* ubase = (const float*)0;
    unsigned long long wf[8], wi[8], wo[8], wc[8];
    {
        const size_t uo = (size_t)h_idx * NH + lane * 16;
#pragma unroll
        for (int j = 0; j < 8; j++) {
            wf[j] = *(const unsigned long long*)(Uf + uo + 2 * j);
            wi[j] = *(const unsigned long long*)(Ui + uo + 2 * j);
            wo[j] = *(const unsigned long long*)(Uo + uo + 2 * j);
            wc[j] = *(const unsigned long long*)(Uc + uo + 2 * j);
        }
    }
    (void)ubase;

    /* gate precompute streams, depth-2 prefetch */
    const float* xf = g_XG + (size_t)(h_idx * 4 + 0) * STEPS;
    const float* xi = g_XG + (size_t)(h_idx * 4 + 1) * STEPS;
    const float* xo = g_XG + (size_t)(h_idx * 4 + 2) * STEPS;
    const float* xc = g_XG + (size_t)(h_idx * 4 + 3) * STEPS;

    float pf0 = __ldcg(xf + 0), pi0 = __ldcg(xi + 0), po0 = __ldcg(xo + 0), pc0 = __ldcg(xc + 0);
    float pf1 = __ldcg(xf + 1), pi1 = __ldcg(xi + 1), po1 = __ldcg(xo + 1), pc1 = __ldcg(xc + 1);

    float c = 0.0f;   /* cell state, replicated across lanes */

    /* smem write slots for this warp's polled quarter (q = w):
       entries e0 = q*128 + 2L, e1 = q*128 + 64 + 2L */
    float* s0 = &sh[SIDX(w * 128 + 2 * lane)];
    float* s1 = &sh[SIDX(w * 128 + 64 + 2 * lane)];
    /* smem read base: lane's 16 contiguous entries */
    const float4* rbase = (const float4*)&sh[SIDX(lane * 16)];

    for (int t = 0; t < STEPS; t++) {
        const int p = t & 1;
        float xgf = p ? pf1 : pf0;
        float xgi = p ? pi1 : pi0;
        float xgo = p ? po1 : po0;
        float xgc = p ? pc1 : pc0;
        if (t + 2 < STEPS) {
            if (p) { pf1 = __ldcg(xf + t + 2); pi1 = __ldcg(xi + t + 2);
                     po1 = __ldcg(xo + t + 2); pc1 = __ldcg(xc + t + 2); }
            else   { pf0 = __ldcg(xf + t + 2); pi0 = __ldcg(xi + t + 2);
                     po0 = __ldcg(xo + t + 2); pc0 = __ldcg(xc + t + 2); }
        }

        /* ---- poll only this warp's quarter of row t ---- */
        const char* qp = (const char*)(g_HP + (size_t)t * NH) + w * 1024 + lane * 16;
        const unsigned tgt = (unsigned)t;
        float4 v0, v1;
        for (;;) {
            v0 = poll_ld(qp);
            v1 = poll_ld(qp + 512);
            bool ok = (__float_as_uint(v0.y) == tgt) & (__float_as_uint(v0.w) == tgt)
                    & (__float_as_uint(v1.y) == tgt) & (__float_as_uint(v1.w) == tgt);
            if (__all_sync(0xffffffffu, ok)) break;
            __nanosleep(30);
        }

        /* strip tags into shared */
        s0[0] = v0.x; s0[1] = v0.z;
        s1[0] = v1.x; s1[1] = v1.z;
        __syncthreads();

        /* ---- load lane's 16 h values (conflict-free), as f32x2 pairs ---- */
        float4 h0 = rbase[0], h1 = rbase[1], h2 = rbase[2], h3 = rbase[3];
        unsigned long long hp[8];
        hp[0] = *(const unsigned long long*)&h0.x;
        hp[1] = *(const unsigned long long*)&h0.z;
        hp[2] = *(const unsigned long long*)&h1.x;
        hp[3] = *(const unsigned long long*)&h1.z;
        hp[4] = *(const unsigned long long*)&h2.x;
        hp[5] = *(const unsigned long long*)&h2.z;
        hp[6] = *(const unsigned long long*)&h3.x;
        hp[7] = *(const unsigned long long*)&h3.z;

        unsigned long long af2 = 0ull, ai2 = 0ull, ao2 = 0ull, ac2 = 0ull;
#pragma unroll
        for (int j = 0; j < 8; j++) {
            ffma2(af2, wf[j], hp[j]);
            ffma2(ai2, wi[j], hp[j]);
            ffma2(ao2, wo[j], hp[j]);
            ffma2(ac2, wc[j], hp[j]);
        }
        float2 pf = *(float2*)&af2;  float af = pf.x + pf.y;
        float2 pi = *(float2*)&ai2;  float ai = pi.x + pi.y;
        float2 po = *(float2*)&ao2;  float ao = po.x + po.y;
        float2 pc = *(float2*)&ac2;  float ac = pc.x + pc.y;

#pragma unroll
        for (int off = 16; off > 0; off >>= 1) {
            af += __shfl_xor_sync(0xffffffffu, af, off);
            ai += __shfl_xor_sync(0xffffffffu, ai, off);
            ao += __shfl_xor_sync(0xffffffffu, ao, off);
            ac += __shfl_xor_sync(0xffffffffu, ac, off);
        }

        float fg = sigmoid_f(af + xgf);
        float ig = sigmoid_f(ai + xgi);
        float og = sigmoid_f(ao + xgo);
        float gg = tanh_f(ac + xgc);
        c = fmaf(fg, c, ig * gg);
        float hval = og * tanh_f(c);

        if (lane == 0) {
            float2 pr = make_float2(hval, __uint_as_float((unsigned)(t + 1)));
            __stcg(&g_HP[(size_t)(t + 1) * NH + h_idx], pr);
        }
    }
}

/* =================== output GEMV =================== */
__global__ void __launch_bounds__(256) out_kernel(
    const float* __restrict__ Ahy, const float* __restrict__ by,
    float* __restrict__ out)
{
    const int w    = threadIdx.x >> 5;
    const int lane = threadIdx.x & 31;
    const int t    = blockIdx.x * 8 + w;
    if (t >= STEPS) return;

    const char* rowp = (const char*)(g_HP + (size_t)(t + 1) * NH) + lane * 16;
    const size_t ab  = 2 * lane;
    float a = 0.0f;
#pragma unroll
    for (int j = 0; j < 8; j++) {
        float4 v = *(const float4*)(rowp + j * 512);
        float2 av = *(const float2*)(Ahy + ab + j * 64);
        a = fmaf(av.x, v.x, a);
        a = fmaf(av.y, v.z, a);
    }
    a += __shfl_xor_sync(0xffffffffu, a, 16);
    a += __shfl_xor_sync(0xffffffffu, a, 8);
    a += __shfl_xor_sync(0xffffffffu, a, 4);
    a += __shfl_xor_sync(0xffffffffu, a, 2);
    a += __shfl_xor_sync(0xffffffffu, a, 1);
    if (lane == 0) out[t] = a + by[0];
}

/* =================== launch =================== */
extern "C" void kernel_launch(void* const* d_in, const int* in_sizes, int n_in,
                              void* d_out, int out_size)
{
    const float* x   = (const float*)d_in[0];
    const float* Wf  = (const float*)d_in[1];
    const float* Uf  = (const float*)d_in[2];
    const float* bf  = (const float*)d_in[3];
    const float* Wi  = (const float*)d_in[4];
    const float* Ui  = (const float*)d_in[5];
    const float* bi  = (const float*)d_in[6];
    const float* Wo  = (const float*)d_in[7];
    const float* Uo  = (const float*)d_in[8];
    const float* bo  = (const float*)d_in[9];
    const float* Wc  = (const float*)d_in[10];
    const float* Uc  = (const float*)d_in[11];
    const float* bc  = (const float*)d_in[12];
    const float* Ahy = (const float*)d_in[13];
    const float* by  = (const float*)d_in[14];
    float* out = (float*)d_out;

    init_kernel<<<1, 512>>>();

    dim3 ggrid((STEPS + GT_TT - 1) / GT_TT, NROWS / GT_ROWS);
    gates_kernel<<<ggrid, GT_TPB>>>(x, Wf, Wi, Wo, Wc, bf, bi, bo, bc);

    rec_kernel<<<NCTA, TPB>>>(Uf, Ui, Uo, Uc);

    out_kernel<<<(STEPS + 7) / 8, 256>>>(Ahy, by, out);
}